// round 4
// baseline (speedup 1.0000x reference)
#include <cuda_runtime.h>

#define S 4096
#define L 16
#define WD 128
#define CD 32
#define NF 5
#define KW 5
#define H 32
#define NTAGS 45
#define IN_DIM (WD + 5)    // 133
#define G4 (4 * H)         // 128
#define TS 32              // sentences per projection tile
#define TSP 36             // padded row stride for proj shared tile

// Scratch (device globals; no allocation allowed)
__device__ float g_rep[S * IN_DIM];        // rep row-major [s][k]
__device__ float g_pre[2][S * G4];         // input projections, layout [s][unit][gate]
__device__ float g_h[2][S * H];            // hidden states

typedef unsigned long long u64;

__device__ __forceinline__ float mufu_tanh(float x) {
    float y;
    asm("tanh.approx.f32 %0, %1;" : "=f"(y) : "f"(x));
    return y;
}
__device__ __forceinline__ float mufu_sigmoid(float x) {
    return fmaf(0.5f, mufu_tanh(0.5f * x), 0.5f);
}
__device__ __forceinline__ u64 pack2(float lo, float hi) {
    u64 r;
    asm("mov.b64 %0, {%1, %2};" : "=l"(r) : "f"(lo), "f"(hi));
    return r;
}
__device__ __forceinline__ void unpack2(float& lo, float& hi, u64 v) {
    asm("mov.b64 {%0, %1}, %2;" : "=f"(lo), "=f"(hi) : "l"(v));
}
__device__ __forceinline__ void fma2(u64& acc, u64 a, u64 b) {
    asm("fma.rn.f32x2 %0, %1, %2, %0;" : "+l"(acc) : "l"(a), "l"(b));
}
__device__ __forceinline__ u64 add2(u64 a, u64 b) {
    u64 r;
    asm("add.rn.f32x2 %0, %1, %2;" : "=l"(r) : "l"(a), "l"(b));
    return r;
}

// ---------------------------------------------------------------------------
// Kernel A: per-word embedding gather + char CNN -> rep (row-major [s][k])
// ---------------------------------------------------------------------------
__global__ __launch_bounds__(128) void rep_kernel(
    const int* __restrict__ word_ids, const int* __restrict__ char_ids,
    const float* __restrict__ word_emb, const float* __restrict__ char_emb,
    const float* __restrict__ conv_w, const float* __restrict__ conv_b)
{
    __shared__ float ce[L][CD];
    __shared__ float conv_sh[NF][L];

    const int s = blockIdx.x;
    const int j = threadIdx.x;

    const int wid = word_ids[s];
    g_rep[s * IN_DIM + j] = word_emb[wid * WD + j];

    #pragma unroll
    for (int i = j; i < L * CD; i += 128) {
        const int l = i / CD, c = i % CD;
        const int cid = char_ids[s * L + l];
        ce[l][c] = char_emb[cid * CD + c];
    }
    __syncthreads();

    if (j < NF * L) {
        const int f = j / L, l = j % L;
        float acc = conv_b[f];
        #pragma unroll
        for (int k = 0; k < KW; k++) {
            const int ll = l + k - 2;
            if (ll >= 0 && ll < L) {
                #pragma unroll
                for (int c = 0; c < CD; c++)
                    acc += ce[ll][c] * conv_w[(f * CD + c) * KW + k];
            }
        }
        conv_sh[f][l] = acc;
    }
    __syncthreads();

    if (j < NF) {
        float m = conv_sh[j][0];
        #pragma unroll
        for (int l = 1; l < L; l++) m = fmaxf(m, conv_sh[j][l]);
        g_rep[s * IN_DIM + WD + j] = m;
    }
}

// ---------------------------------------------------------------------------
// Kernel A2: input projection GEMM. Writes pre in [s][unit][gate] layout.
// ---------------------------------------------------------------------------
__global__ __launch_bounds__(256) void proj_kernel(
    const float* __restrict__ w_ih_f, const float* __restrict__ b_ih_f,
    const float* __restrict__ b_hh_f,
    const float* __restrict__ w_ih_b, const float* __restrict__ b_ih_b,
    const float* __restrict__ b_hh_b)
{
    __shared__ float rt_sh[IN_DIM][TSP];   // transposed tile, padded rows

    const int s0  = blockIdx.x * TS;
    const int o   = threadIdx.x;
    const int dir = o >> 7;
    const int j   = o & 127;          // gate row: 0..31 i, 32..63 f, ...

    // stage: coalesced gmem reads (k fastest), transposed shared writes
    for (int i = o; i < TS * IN_DIM; i += 256) {
        const int s = i / IN_DIM, k = i % IN_DIM;
        rt_sh[k][s] = g_rep[(s0 + s) * IN_DIM + k];
    }
    __syncthreads();

    const float bias = dir ? (b_ih_b[j] + b_hh_b[j]) : (b_ih_f[j] + b_hh_f[j]);
    const float* __restrict__ wrow = (dir ? w_ih_b : w_ih_f) + j * IN_DIM;

    float acc[TS];
    #pragma unroll
    for (int i = 0; i < TS; i++) acc[i] = bias;

    for (int k = 0; k < IN_DIM; k++) {
        const float w = __ldg(&wrow[k]);
        const float4* r4 = (const float4*)&rt_sh[k][0];
        #pragma unroll
        for (int q = 0; q < TS / 4; q++) {
            const float4 r = r4[q];
            acc[4 * q + 0] = fmaf(w, r.x, acc[4 * q + 0]);
            acc[4 * q + 1] = fmaf(w, r.y, acc[4 * q + 1]);
            acc[4 * q + 2] = fmaf(w, r.z, acc[4 * q + 2]);
            acc[4 * q + 3] = fmaf(w, r.w, acc[4 * q + 3]);
        }
    }

    // interleaved write: pre[s*128 + unit*4 + gate]
    const int unit = j & 31, gate = j >> 5;
    float* __restrict__ pre = g_pre[dir];
    #pragma unroll
    for (int i = 0; i < TS; i++)
        pre[(s0 + i) * G4 + unit * 4 + gate] = acc[i];
}

// ---------------------------------------------------------------------------
// Kernel B: LSTM scan, ONE WARP per direction, zero block barriers.
// Lane l owns unit l (all 4 w_hh gate rows in registers as f32x2 pairs).
// h broadcast via ping-pong shared buffer: 1 STS + syncwarp + 8 LDS.128.
// Gates via fma.rn.f32x2, 2-way split accumulator chains. pre prefetched
// 2 steps ahead to hide L2 latency.
// ---------------------------------------------------------------------------
__global__ __launch_bounds__(32, 1) void lstm_scan_kernel(
    const float* __restrict__ w_hh_f, const float* __restrict__ w_hh_b)
{
    const int dir  = blockIdx.x;
    const int lane = threadIdx.x;    // unit index 0..31

    const float* __restrict__ w_hh = dir ? w_hh_b : w_hh_f;
    const float4* __restrict__ pre4 = (const float4*)g_pre[dir];
    float* __restrict__ hout        = g_h[dir];

    __shared__ float hbuf[2][H];

    // Load gate rows for this unit, packed as f32x2 pairs
    u64 wi[H / 2], wf[H / 2], wg[H / 2], wo[H / 2];
    #pragma unroll
    for (int m = 0; m < H / 2; m++) {
        wi[m] = pack2(w_hh[(0 * H + lane) * H + 2 * m], w_hh[(0 * H + lane) * H + 2 * m + 1]);
        wf[m] = pack2(w_hh[(1 * H + lane) * H + 2 * m], w_hh[(1 * H + lane) * H + 2 * m + 1]);
        wg[m] = pack2(w_hh[(2 * H + lane) * H + 2 * m], w_hh[(2 * H + lane) * H + 2 * m + 1]);
        wo[m] = pack2(w_hh[(3 * H + lane) * H + 2 * m], w_hh[(3 * H + lane) * H + 2 * m + 1]);
    }

    float h = 0.0f, c = 0.0f;

    // 2-deep prefetch of pre
    const int i0 = dir ? (S - 1) : 0;
    const int i1 = dir ? (S - 2) : 1;
    float4 pv0 = pre4[i0 * (G4 / 4) + lane];
    float4 pv1 = pre4[i1 * (G4 / 4) + lane];

    for (int t = 0; t < S; t++) {
        const int cur = dir ? (S - 1 - t) : t;
        const float4 p = pv0;
        pv0 = pv1;
        if (t + 2 < S) {
            const int nxt = dir ? (S - 3 - t) : (t + 2);
            pv1 = pre4[nxt * (G4 / 4) + lane];
        }

        // publish h(t) and read all 32 via broadcast LDS.128
        const int b = t & 1;
        hbuf[b][lane] = h;
        __syncwarp();

        // 2-way split accumulator chains per gate
        u64 ai0 = pack2(p.x, 0.0f), ai1 = pack2(0.0f, 0.0f);
        u64 af0 = pack2(p.y, 0.0f), af1 = pack2(0.0f, 0.0f);
        u64 ag0 = pack2(p.z, 0.0f), ag1 = pack2(0.0f, 0.0f);
        u64 ao0 = pack2(p.w, 0.0f), ao1 = pack2(0.0f, 0.0f);

        const float4* __restrict__ hb4 = (const float4*)hbuf[b];
        #pragma unroll
        for (int q = 0; q < 8; q++) {
            const float4 hv = hb4[q];           // broadcast LDS.128
            const u64 hA = pack2(hv.x, hv.y);
            const u64 hB = pack2(hv.z, hv.w);
            fma2(ai0, wi[2 * q], hA); fma2(ai1, wi[2 * q + 1], hB);
            fma2(af0, wf[2 * q], hA); fma2(af1, wf[2 * q + 1], hB);
            fma2(ag0, wg[2 * q], hA); fma2(ag1, wg[2 * q + 1], hB);
            fma2(ao0, wo[2 * q], hA); fma2(ao1, wo[2 * q + 1], hB);
        }

        float lo, hi;
        unpack2(lo, hi, add2(ai0, ai1)); const float gi = mufu_sigmoid(lo + hi);
        unpack2(lo, hi, add2(af0, af1)); const float gf = mufu_sigmoid(lo + hi);
        unpack2(lo, hi, add2(ag0, ag1)); const float gg = mufu_tanh(lo + hi);
        unpack2(lo, hi, add2(ao0, ao1)); const float go = mufu_sigmoid(lo + hi);

        c = fmaf(gf, c, gi * gg);
        h = go * mufu_tanh(c);

        hout[cur * H + lane] = h;
    }
}

// ---------------------------------------------------------------------------
// Kernel C: output projection, shared-staged. Block = 32 sentences.
// ---------------------------------------------------------------------------
__global__ __launch_bounds__(256) void out_kernel(
    const float* __restrict__ out_w, const float* __restrict__ out_b,
    float* __restrict__ out)
{
    __shared__ float hsh[32][66];          // [s][hf(0:32)|hb(32:64)], padded
    __shared__ float wsh[NTAGS * 65];      // [n][k], padded rows
    __shared__ float bsh[NTAGS];

    const int s0  = blockIdx.x * 32;
    const int tid = threadIdx.x;

    for (int i = tid; i < 32 * H; i += 256) {
        const int s = i >> 5, k = i & 31;
        hsh[s][k]      = g_h[0][(s0 + s) * H + k];
        hsh[s][32 + k] = g_h[1][(s0 + s) * H + k];
    }
    for (int i = tid; i < NTAGS * 2 * H; i += 256)
        wsh[(i >> 6) * 65 + (i & 63)] = out_w[i];
    if (tid < NTAGS) bsh[tid] = out_b[tid];
    __syncthreads();

    for (int o = tid; o < 32 * NTAGS; o += 256) {
        const int s = o / NTAGS, n = o % NTAGS;
        float acc = bsh[n];
        const float* __restrict__ hv = hsh[s];
        const float* __restrict__ wv = &wsh[n * 65];
        #pragma unroll
        for (int k = 0; k < 2 * H; k++) acc = fmaf(hv[k], wv[k], acc);
        out[(s0 + s) * NTAGS + n] = acc;
    }
}

// ---------------------------------------------------------------------------
extern "C" void kernel_launch(void* const* d_in, const int* in_sizes, int n_in,
                              void* d_out, int out_size)
{
    const int*   word_ids = (const int*)  d_in[0];
    const int*   char_ids = (const int*)  d_in[1];
    const float* word_emb = (const float*)d_in[2];
    const float* char_emb = (const float*)d_in[3];
    const float* conv_w   = (const float*)d_in[4];
    const float* conv_b   = (const float*)d_in[5];
    const float* w_ih_f   = (const float*)d_in[6];
    const float* w_hh_f   = (const float*)d_in[7];
    const float* b_ih_f   = (const float*)d_in[8];
    const float* b_hh_f   = (const float*)d_in[9];
    const float* w_ih_b   = (const float*)d_in[10];
    const float* w_hh_b   = (const float*)d_in[11];
    const float* b_ih_b   = (const float*)d_in[12];
    const float* b_hh_b   = (const float*)d_in[13];
    const float* out_w    = (const float*)d_in[14];
    const float* out_b    = (const float*)d_in[15];
    float* out = (float*)d_out;

    rep_kernel<<<S, 128>>>(word_ids, char_ids, word_emb, char_emb,
                           conv_w, conv_b);
    proj_kernel<<<S / TS, 256>>>(w_ih_f, b_ih_f, b_hh_f,
                                 w_ih_b, b_ih_b, b_hh_b);
    lstm_scan_kernel<<<2, 32>>>(w_hh_f, w_hh_b);
    out_kernel<<<S / 32, 256>>>(out_w, out_b, out);
}